// round 4
// baseline (speedup 1.0000x reference)
#include <cuda_runtime.h>
#include <cuda_bf16.h>
#include <math.h>

#define Bz   128
#define LCz  512
#define LEz  512
#define Hz   512
#define Vz   128
#define TDEC 511
#define NBLK 128
#define BHS  (Bz * Hz)   // 65536

// ---------------- static device scratch (no runtime allocation) -------------
__device__ __align__(16) float g_h[2][BHS];
__device__ __align__(16) float g_c[BHS];
__device__ __align__(16) float g_vp[4][BHS];   // V partials (K-split out-proj)
__device__ __align__(16) float g_qp[4][BHS];   // q partials (K-split att-proj)
__device__ __align__(16) float g_attn[BHS];
__device__ __align__(16) __nv_bfloat16 g_enc[(size_t)Bz * LCz * Hz];  // 67 MB
__device__ float g_nll[Bz * TDEC];
__device__ float g_msk[Bz * TDEC];
__device__ float g_ps[NBLK], g_pc[NBLK];
__device__ unsigned g_arrive;
__device__ volatile unsigned g_gen;

__device__ __forceinline__ float sigm(float x) { return 1.f / (1.f + expf(-x)); }

// ---------------- software grid barrier (all 128 blocks co-resident) --------
__device__ __forceinline__ void gsync() {
    __syncthreads();
    if (threadIdx.x == 0) {
        __threadfence();                         // release (writes -> L2)
        unsigned gen = g_gen;
        if (atomicAdd(&g_arrive, 1u) == NBLK - 1u) {
            g_arrive = 0u;
            __threadfence();                     // reset before gen flip
            g_gen = gen + 1u;
        } else {
            while (g_gen == gen) __nanosleep(64);
        }
        __threadfence();                         // acquire (invalidates L1)
    }
    __syncthreads();
}

// ---------------- GEMM segment: 32m x 64n tile, 256 threads -----------------
// acc[r][i]: r = m-subrow (2 per thread), i = n-subcol (4 per thread).
// LSTM=true : 64 n = 16 j-cols x 4 gates interleaved (col = jj*4 + gate).
// SUMV=true : A element = sum of 4 K-split partial arrays (stride BHS).
template <bool LSTM, bool SUMV>
__device__ __forceinline__ void seg_accum(
    const float* __restrict__ A, int lda,
    const float* __restrict__ W, int ldw, int K,
    float acc[2][4], float* sm)
{
    float (*As)[32] = (float (*)[32])sm;            // 16 x 32
    float (*Ws)[64] = (float (*)[64])(sm + 512);    // 16 x 64
    int tid = threadIdx.x;
    int cg = tid & 15, bg = tid >> 4;
    int ar = tid >> 2, k4 = tid & 3;                // A loader: rows 0..31 (tid<128)
    int wr = tid >> 2;                              // W loader: rows 0..63
    int wrow, wcol;
    if (LSTM) { int gg = wr >> 4, jj = wr & 15; wrow = gg * Hz + jj; wcol = jj * 4 + gg; }
    else      { wrow = wr; wcol = wr; }
    const float* wp = W + (size_t)wrow * ldw + k4 * 4;
    const float* ap = A + (size_t)(tid < 128 ? ar : 0) * lda + k4 * 4;

    for (int k0 = 0; k0 < K; k0 += 16) {
        if (tid < 128) {
            float4 av = *(const float4*)(ap + k0);
            if (SUMV) {
                float4 a1 = *(const float4*)(ap + k0 + BHS);
                float4 a2 = *(const float4*)(ap + k0 + 2 * BHS);
                float4 a3 = *(const float4*)(ap + k0 + 3 * BHS);
                av.x += a1.x + a2.x + a3.x;
                av.y += a1.y + a2.y + a3.y;
                av.z += a1.z + a2.z + a3.z;
                av.w += a1.w + a2.w + a3.w;
            }
            As[k4 * 4 + 0][ar] = av.x;
            As[k4 * 4 + 1][ar] = av.y;
            As[k4 * 4 + 2][ar] = av.z;
            As[k4 * 4 + 3][ar] = av.w;
        }
        {
            float4 wv = *(const float4*)(wp + k0);
            Ws[k4 * 4 + 0][wcol] = wv.x;
            Ws[k4 * 4 + 1][wcol] = wv.y;
            Ws[k4 * 4 + 2][wcol] = wv.z;
            Ws[k4 * 4 + 3][wcol] = wv.w;
        }
        __syncthreads();
        #pragma unroll
        for (int kk = 0; kk < 16; kk++) {
            float a0 = As[kk][bg * 2];
            float a1 = As[kk][bg * 2 + 1];
            float4 w = *(const float4*)&Ws[kk][cg * 4];
            acc[0][0] += a0 * w.x; acc[0][1] += a0 * w.y; acc[0][2] += a0 * w.z; acc[0][3] += a0 * w.w;
            acc[1][0] += a1 * w.x; acc[1][1] += a1 * w.y; acc[1][2] += a1 * w.z; acc[1][3] += a1 * w.w;
        }
        __syncthreads();
    }
}

// ---------------- LSTM cell epilogue ---------------------------------------
__device__ __forceinline__ void cell_epi(
    float acc[2][4], int m0, int j0,
    const float* __restrict__ bih, const float* __restrict__ bhh,
    float* __restrict__ hout, bool enc_store, int t)
{
    int tid = threadIdx.x, cg = tid & 15, bg = tid >> 4;
    int j = j0 + cg;
    float b0 = bih[j]          + bhh[j];
    float b1 = bih[Hz + j]     + bhh[Hz + j];
    float b2 = bih[2 * Hz + j] + bhh[2 * Hz + j];
    float b3 = bih[3 * Hz + j] + bhh[3 * Hz + j];
    #pragma unroll
    for (int r = 0; r < 2; r++) {
        int b = m0 + bg * 2 + r;
        float xi = acc[r][0] + b0;
        float xf = acc[r][1] + b1;
        float xg = acc[r][2] + b2;
        float xo = acc[r][3] + b3;
        float c  = g_c[b * Hz + j];
        float cn = sigm(xf) * c + sigm(xi) * tanhf(xg);
        float hn = sigm(xo) * tanhf(cn);
        g_c[b * Hz + j] = cn;
        hout[b * Hz + j] = hn;
        if (enc_store)
            g_enc[((size_t)b * LCz + t) * Hz + j] = __float2bfloat16(hn);
    }
}

// ---------------- plain epilogue -------------------------------------------
__device__ __forceinline__ void plain_epi(
    float acc[2][4], float* __restrict__ outp, int m0, int n0,
    const float* __restrict__ bias)
{
    int tid = threadIdx.x, cg = tid & 15, bg = tid >> 4;
    #pragma unroll
    for (int r = 0; r < 2; r++) {
        int b = m0 + bg * 2 + r;
        #pragma unroll
        for (int i = 0; i < 4; i++) {
            int n = n0 + cg * 4 + i;
            float v = acc[r][i];
            if (bias) v += bias[n];
            outp[b * Hz + n] = v;
        }
    }
}

// ---------------- per-batch attention (two-pass, pad-skip) ------------------
__device__ void attn_block(int b, const int* __restrict__ C_pad, float* sm)
{
    float* sq  = sm;          // 512
    float* ss  = sm + 512;    // 512
    float* red = sm + 1024;   // 8
    float* sca = sm + 1040;   // 2
    int tid = threadIdx.x, lane = tid & 31, w = tid >> 5;

    const float* qp = (const float*)g_qp;
    for (int i = tid; i < Hz; i += 256)
        sq[i] = qp[b * Hz + i] + qp[BHS + b * Hz + i]
              + qp[2 * BHS + b * Hz + i] + qp[3 * BHS + b * Hz + i];
    __syncthreads();

    float qreg[16];
    #pragma unroll
    for (int i = 0; i < 16; i++) qreg[i] = sq[lane * 16 + i];

    const __nv_bfloat16* eb = g_enc + (size_t)b * LCz * Hz;
    for (int l = w; l < LCz; l += 8) {
        float sc = -INFINITY;
        if (C_pad[b * LCz + l] == 0) {
            const __nv_bfloat16* row = eb + (size_t)l * Hz + lane * 16;
            uint4 u0 = *(const uint4*)row;
            uint4 u1 = *(const uint4*)(row + 8);
            const __nv_bfloat162* h0 = (const __nv_bfloat162*)&u0;
            const __nv_bfloat162* h1 = (const __nv_bfloat162*)&u1;
            float acc = 0.f;
            #pragma unroll
            for (int i = 0; i < 4; i++) {
                float2 f0 = __bfloat1622float2(h0[i]);
                float2 f1 = __bfloat1622float2(h1[i]);
                acc += f0.x * qreg[2 * i]     + f0.y * qreg[2 * i + 1];
                acc += f1.x * qreg[8 + 2 * i] + f1.y * qreg[8 + 2 * i + 1];
            }
            #pragma unroll
            for (int o = 16; o > 0; o >>= 1) acc += __shfl_xor_sync(0xffffffffu, acc, o);
            sc = acc;
        }
        if (lane == 0) ss[l] = sc;
    }
    __syncthreads();

    float m = -INFINITY;
    for (int l = tid; l < LCz; l += 256) m = fmaxf(m, ss[l]);
    #pragma unroll
    for (int o = 16; o > 0; o >>= 1) m = fmaxf(m, __shfl_xor_sync(0xffffffffu, m, o));
    if (lane == 0) red[w] = m;
    __syncthreads();
    if (tid == 0) {
        float mm = red[0];
        for (int i = 1; i < 8; i++) mm = fmaxf(mm, red[i]);
        sca[0] = mm;
    }
    __syncthreads();
    float bmax = sca[0];

    float s = 0.f;
    for (int l = tid; l < LCz; l += 256) {
        float v = ss[l];
        float e = (v == -INFINITY) ? 0.f : expf(v - bmax);
        ss[l] = e;
        s += e;
    }
    #pragma unroll
    for (int o = 16; o > 0; o >>= 1) s += __shfl_xor_sync(0xffffffffu, s, o);
    if (lane == 0) red[w] = s;
    __syncthreads();
    if (tid == 0) {
        float t2 = 0.f;
        for (int i = 0; i < 8; i++) t2 += red[i];
        sca[1] = t2;
    }
    __syncthreads();
    float inv = 1.f / sca[1];

    float a0 = 0.f, a1 = 0.f;
    for (int l = 0; l < LCz; l++) {
        float d = ss[l];
        if (d == 0.f) continue;
        __nv_bfloat162 p = *(const __nv_bfloat162*)(eb + (size_t)l * Hz + 2 * tid);
        float2 f = __bfloat1622float2(p);
        a0 += d * f.x;
        a1 += d * f.y;
    }
    g_attn[b * Hz + 2 * tid]     = a0 * inv;
    g_attn[b * Hz + 2 * tid + 1] = a1 * inv;
}

// ---------------- per-batch logits + masked CE ------------------------------
__device__ void logits_ce(int b, int tt, const int* __restrict__ E,
                          const float* __restrict__ voc_W,
                          const float* __restrict__ voc_b, float* sm)
{
    float* st = sm;          // 512
    float* sl = sm + 512;    // 128
    int tid = threadIdx.x, lane = tid & 31, w = tid >> 5;
    __syncthreads();  // guard smem reuse

    const float* vp = (const float*)g_vp;
    for (int i = tid; i < Hz; i += 256) {
        float v = vp[b * Hz + i] + vp[BHS + b * Hz + i]
                + vp[2 * BHS + b * Hz + i] + vp[3 * BHS + b * Hz + i];
        st[i] = tanhf(v);
    }
    __syncthreads();

    float sreg[16];
    #pragma unroll
    for (int i = 0; i < 16; i++) sreg[i] = st[lane * 16 + i];

    for (int v = w; v < Vz; v += 8) {
        const float* wr = voc_W + (size_t)v * Hz + lane * 16;
        float acc = 0.f;
        #pragma unroll
        for (int i = 0; i < 16; i += 4) {
            float4 x = *(const float4*)(wr + i);
            acc += x.x * sreg[i] + x.y * sreg[i + 1] + x.z * sreg[i + 2] + x.w * sreg[i + 3];
        }
        #pragma unroll
        for (int o = 16; o > 0; o >>= 1) acc += __shfl_xor_sync(0xffffffffu, acc, o);
        if (lane == 0) sl[v] = acc + voc_b[v];
    }
    __syncthreads();

    if (w == 0) {
        float m = -INFINITY;
        for (int v = lane; v < Vz; v += 32) m = fmaxf(m, sl[v]);
        #pragma unroll
        for (int o = 16; o > 0; o >>= 1) m = fmaxf(m, __shfl_xor_sync(0xffffffffu, m, o));
        float s = 0.f;
        for (int v = lane; v < Vz; v += 32) s += expf(sl[v] - m);
        #pragma unroll
        for (int o = 16; o > 0; o >>= 1) s += __shfl_xor_sync(0xffffffffu, s, o);
        if (lane == 0) {
            int tv = E[b * LEz + tt + 1];
            int idx = b * TDEC + tt;
            if (tv != 0) { g_nll[idx] = m + logf(s) - sl[tv]; g_msk[idx] = 1.f; }
            else         { g_nll[idx] = 0.f;                  g_msk[idx] = 0.f; }
        }
    }
}

// ---------------- the single persistent kernel ------------------------------
__global__ void __launch_bounds__(256, 1) persist_kernel(
    const float* __restrict__ C,       const int* __restrict__ C_pad,
    const int* __restrict__ E,         const float* __restrict__ E_emb,
    const float* __restrict__ enc_Wih, const float* __restrict__ enc_Whh,
    const float* __restrict__ enc_bih, const float* __restrict__ enc_bhh,
    const float* __restrict__ dec_Wih, const float* __restrict__ dec_Whh,
    const float* __restrict__ dec_bih, const float* __restrict__ dec_bhh,
    const float* __restrict__ att_W,   const float* __restrict__ out_W,
    const float* __restrict__ out_b,   const float* __restrict__ voc_W,
    const float* __restrict__ voc_b,   float* __restrict__ out)
{
    __shared__ float sm[1600];
    int bid = blockIdx.x, tid = threadIdx.x;
    int lane = tid & 31, w = tid >> 5;

    // ---- init state ----
    for (int i = bid * 256 + tid; i < BHS; i += NBLK * 256) { g_h[0][i] = 0.f; g_c[i] = 0.f; }
    float* vpf = (float*)g_vp;
    for (int i = bid * 256 + tid; i < 4 * BHS; i += NBLK * 256) vpf[i] = 0.f;
    gsync();

    int m0 = (bid & 3) * 32;        // gates-tile batch offset
    int j0 = (bid >> 2) * 16;       // gates-tile j offset

    // ---- encoder: 512 fused steps ----
    for (int t = 0; t < LCz; t++) {
        const float* hin = g_h[t & 1];
        float* hout = g_h[1 - (t & 1)];
        float acc[2][4] = {};
        seg_accum<true, false>(C + (size_t)m0 * LCz * Vz + (size_t)t * Vz, LCz * Vz,
                               enc_Wih + (size_t)j0 * Vz, Vz, Vz, acc, sm);
        seg_accum<true, false>(hin + m0 * Hz, Hz,
                               enc_Whh + (size_t)j0 * Hz, Hz, Hz, acc, sm);
        cell_epi(acc, m0, j0, enc_bih, enc_bhh, hout, true, t);
        gsync();
    }

    // ---- decoder: 511 steps, 4 phases each ----
    int ks = bid & 3, kr = bid >> 2;
    int km0 = (kr & 3) * 32, kn0 = (kr >> 2) * 64;
    for (int t = 0; t < TDEC; t++) {
        const float* hin = g_h[t & 1];
        float* hout = g_h[1 - (t & 1)];

        // P1: gates = Xemb + Vprev(sum of partials)@Wih_v + h@Whh ; cell
        {
            float acc[2][4] = {};
            seg_accum<true, false>(E_emb + (size_t)m0 * LEz * Vz + (size_t)t * Vz, LEz * Vz,
                                   dec_Wih + (size_t)j0 * (Vz + Hz), Vz + Hz, Vz, acc, sm);
            seg_accum<true, true >((const float*)g_vp + m0 * Hz, Hz,
                                   dec_Wih + (size_t)j0 * (Vz + Hz) + Vz, Vz + Hz, Hz, acc, sm);
            seg_accum<true, false>(hin + m0 * Hz, Hz,
                                   dec_Whh + (size_t)j0 * Hz, Hz, Hz, acc, sm);
            cell_epi(acc, m0, j0, dec_bih, dec_bhh, hout, false, 0);
        }
        gsync();

        // P2: q partials (K-split x4 so all SMs work)
        {
            float acc[2][4] = {};
            seg_accum<false, false>(hout + km0 * Hz + ks * 128, Hz,
                                    att_W + (size_t)kn0 * Hz + ks * 128, Hz, 128, acc, sm);
            plain_epi(acc, g_qp[ks], km0, kn0, nullptr);
        }
        gsync();

        // P3: attention for batch=bid  +  logits/CE of step t-1
        attn_block(bid, C_pad, sm);
        if (t > 0) logits_ce(bid, t - 1, E, voc_W, voc_b, sm);
        gsync();

        // P4: out-proj partials (K-split x4); bias folded into split 0
        {
            const float* Asrc = (ks < 2) ? hout : g_attn;
            int koff = (ks & 1) * 256;
            float acc[2][4] = {};
            seg_accum<false, false>(Asrc + km0 * Hz + koff, Hz,
                                    out_W + (size_t)kn0 * (2 * Hz) + ks * 256, 2 * Hz, 256, acc, sm);
            plain_epi(acc, g_vp[ks], km0, kn0, (ks == 0) ? out_b : nullptr);
        }
        gsync();
    }

    // ---- last step's logits/CE ----
    logits_ce(bid, TDEC - 1, E, voc_W, voc_b, sm);
    gsync();

    // ---- deterministic reduction: block bid handles batch bid ----
    {
        float s = 0.f, c = 0.f;
        for (int i = tid; i < TDEC; i += 256) {
            s += g_nll[bid * TDEC + i];
            c += g_msk[bid * TDEC + i];
        }
        #pragma unroll
        for (int o = 16; o > 0; o >>= 1) {
            s += __shfl_xor_sync(0xffffffffu, s, o);
            c += __shfl_xor_sync(0xffffffffu, c, o);
        }
        __syncthreads();
        if (lane == 0) { sm[w] = s; sm[8 + w] = c; }
        __syncthreads();
        if (tid == 0) {
            float ts = 0.f, tc = 0.f;
            for (int i = 0; i < 8; i++) { ts += sm[i]; tc += sm[8 + i]; }
            g_ps[bid] = ts; g_pc[bid] = tc;
        }
    }
    gsync();
    if (bid == 0 && tid == 0) {
        float ts = 0.f, tc = 0.f;
        for (int i = 0; i < NBLK; i++) { ts += g_ps[i]; tc += g_pc[i]; }
        out[0] = ts / fmaxf(tc, 1.f);
    }
}

// ---------------- host entry (single launch => 1-node graph) ----------------
extern "C" void kernel_launch(void* const* d_in, const int* in_sizes, int n_in,
                              void* d_out, int out_size)
{
    persist_kernel<<<NBLK, 256>>>(
        (const float*)d_in[0],  (const int*)d_in[1],
        (const int*)d_in[2],    (const float*)d_in[3],
        (const float*)d_in[4],  (const float*)d_in[5],
        (const float*)d_in[6],  (const float*)d_in[7],
        (const float*)d_in[8],  (const float*)d_in[9],
        (const float*)d_in[10], (const float*)d_in[11],
        (const float*)d_in[12], (const float*)d_in[13],
        (const float*)d_in[14], (const float*)d_in[15],
        (const float*)d_in[16], (float*)d_out);
}

// round 5
// speedup vs baseline: 1.3455x; 1.3455x over previous
#include <cuda_runtime.h>
#include <cuda_bf16.h>
#include <math.h>
#include <stdint.h>

#define Bz   128
#define LCz  512
#define LEz  512
#define Hz   512
#define Vz   128
#define TDEC 511
#define NBLK 128
#define BHS  (Bz * Hz)   // 65536

// dynamic smem layout (float4 units):
//   Wp  [0,     9216)  : W fragment pack (2 wn * 144 ksteps * 32 lanes)
//   Ab  [9216, 10240)  : A staging, 2 buffers of 64x8 float4
//   scr [10240,10752)  : 2048 floats generic scratch
#define SMEM_BYTES 172032

// ---------------- static device scratch -------------------------------------
__device__ __align__(16) float g_h[2][BHS];
__device__ __align__(16) float g_c[BHS];
__device__ __align__(16) float g_vp[4][BHS];   // V partials (K-split out-proj)
__device__ __align__(16) float g_qp[4][BHS];   // q partials (K-split att-proj)
__device__ __align__(16) float g_attn[BHS];
__device__ __align__(16) __nv_bfloat16 g_enc[(size_t)Bz * LCz * Hz];  // 67 MB
__device__ float g_nll[Bz * TDEC];
__device__ float g_msk[Bz * TDEC];
__device__ float g_ps[NBLK], g_pc[NBLK];
__device__ unsigned g_arrive;
__device__ volatile unsigned g_gen;

__device__ __forceinline__ float sigm(float x) { return 1.f / (1.f + expf(-x)); }

__device__ __forceinline__ uint32_t s2u(const void* p) {
    return (uint32_t)__cvta_generic_to_shared(p);
}
__device__ __forceinline__ uint32_t f2tf32(uint32_t raw) {
    uint32_t u;
    float x = __uint_as_float(raw);
    asm("cvt.rna.tf32.f32 %0, %1;" : "=r"(u) : "f"(x));
    return u;
}
__device__ __forceinline__ void mma8(float acc[4],
    uint32_t a0, uint32_t a1, uint32_t a2, uint32_t a3,
    uint32_t b0, uint32_t b1)
{
    asm volatile("mma.sync.aligned.m16n8k8.row.col.f32.tf32.tf32.f32 "
        "{%0,%1,%2,%3},{%4,%5,%6,%7},{%8,%9},{%0,%1,%2,%3};"
        : "+f"(acc[0]), "+f"(acc[1]), "+f"(acc[2]), "+f"(acc[3])
        : "r"(a0), "r"(a1), "r"(a2), "r"(a3), "r"(b0), "r"(b1));
}

// ---------------- software grid barrier -------------------------------------
__device__ __forceinline__ void gsync() {
    __syncthreads();
    if (threadIdx.x == 0) {
        __threadfence();
        unsigned gen = g_gen;
        if (atomicAdd(&g_arrive, 1u) == NBLK - 1u) {
            g_arrive = 0u;
            __threadfence();
            g_gen = gen + 1u;
        } else {
            while (g_gen == gen) __nanosleep(64);
        }
        __threadfence();
    }
    __syncthreads();
}

// ---------------- W fragment pack (once per phase) --------------------------
// Block owns j-range [nb*8, nb*8+8). Warp wn in {0,1} owns warp-cols c=0..15,
// c -> jj = wn*4 + (c>>2), gate = c&3, W row = gate*Hz + nb*8 + jj.
// Pack entry (wn, s, lane) = float4 {b0h0, b1h0, b0h1, b1h1} in tf32.
__device__ void pack_W(float4* Wp, int nb, int KS, int Kih,
                       const float* __restrict__ Wih, int ldih,
                       const float* __restrict__ Whh, int ldhh)
{
    for (int idx = threadIdx.x; idx < 2 * KS * 32; idx += 256) {
        int wn  = idx / (KS * 32);
        int rem = idx - wn * (KS * 32);
        int s = rem >> 5, l = rem & 31;
        int gid = l >> 2, tig = l & 3;
        int k0 = s * 8 + tig, k1 = k0 + 4;
        float v[4];
        #pragma unroll
        for (int hh = 0; hh < 2; hh++) {
            int c = hh * 8 + gid;
            int jj = wn * 4 + (c >> 2);
            int gate = c & 3;
            int grow = gate * Hz + nb * 8 + jj;
            const float* pi = Wih + (size_t)grow * ldih;
            const float* ph = Whh + (size_t)grow * ldhh;
            v[hh * 2]     = (k0 < Kih) ? pi[k0] : ph[k0 - Kih];
            v[hh * 2 + 1] = (k1 < Kih) ? pi[k1] : ph[k1 - Kih];
        }
        float4 o;
        o.x = __uint_as_float(f2tf32(__float_as_uint(v[0])));
        o.y = __uint_as_float(f2tf32(__float_as_uint(v[1])));
        o.z = __uint_as_float(f2tf32(__float_as_uint(v[2])));
        o.w = __uint_as_float(f2tf32(__float_as_uint(v[3])));
        Wp[idx] = o;
    }
}

// ---------------- A chunk loader (2 float4 per thread) ----------------------
template<bool DEC>
__device__ __forceinline__ void loadA(float4& r0, float4& r1, int cc,
    const float* __restrict__ xrow, const float* __restrict__ hrow,
    const float* __restrict__ vrow, int quad)
{
    #pragma unroll
    for (int u = 0; u < 2; u++) {
        int kf4 = cc * 8 + quad * 2 + u;
        float4 v;
        if (DEC) {
            if (kf4 < 32) {
                v = *(const float4*)(xrow + kf4 * 4);
            } else if (kf4 < 160) {
                int off = kf4 * 4 - 128;
                float4 a = *(const float4*)(vrow + off);
                float4 b = *(const float4*)(vrow + off + BHS);
                float4 c = *(const float4*)(vrow + off + 2 * BHS);
                float4 d = *(const float4*)(vrow + off + 3 * BHS);
                v.x = a.x + b.x + c.x + d.x;
                v.y = a.y + b.y + c.y + d.y;
                v.z = a.z + b.z + c.z + d.z;
                v.w = a.w + b.w + c.w + d.w;
            } else {
                v = *(const float4*)(hrow + kf4 * 4 - 640);
            }
        } else {
            if (kf4 < 32) v = *(const float4*)(xrow + kf4 * 4);
            else          v = *(const float4*)(hrow + kf4 * 4 - 128);
        }
        if (u == 0) r0 = v; else r1 = v;
    }
}

// ---------------- fused gates GEMM (tf32 mma) + LSTM cell -------------------
// Block tile: M=64 (batch half mh), N=32 gate-rows (j-range nb*8..+8, 4 gates).
// 8 warps = 4 wm (m16) x 2 wn (n16). K = DEC?1152:640, chunks of 32.
template<bool DEC>
__device__ __forceinline__ void gates_step(
    const float4* __restrict__ Wp, float4* __restrict__ Ab,
    const float* __restrict__ xbase, int t,
    const float* __restrict__ hin, float* __restrict__ hout,
    int mh, int nb, const float bias[2][4])
{
    const int NCH = DEC ? 36 : 20;
    const int KS  = DEC ? 144 : 80;
    int tid = threadIdx.x;
    int l = tid & 31, wrp = tid >> 5;
    int wm = wrp & 3, wn = wrp >> 2;
    int gid = l >> 2, t0 = l & 3;
    int quad = tid & 3, mrow = tid >> 2;
    int m16 = mh * 64 + wm * 16;
    int arow = wm * 16 + ((l >> 3) & 1) * 8 + (l & 7);
    int halfsel = l >> 4;

    int bS = mh * 64 + mrow;
    const float* xrow = xbase + ((size_t)bS * (DEC ? LEz : LCz) + t) * Vz;
    const float* hrow = hin + bS * Hz;
    const float* vrow = (const float*)g_vp + bS * Hz;

    float acc[2][4];
    #pragma unroll
    for (int i = 0; i < 2; i++)
        #pragma unroll
        for (int k = 0; k < 4; k++) acc[i][k] = 0.f;

    float4 r0, r1;
    loadA<DEC>(r0, r1, 0, xrow, hrow, vrow, quad);
    {
        int c0 = quad * 2;
        Ab[mrow * 8 + (c0 ^ (mrow & 7))] = r0;
        Ab[mrow * 8 + ((c0 + 1) ^ (mrow & 7))] = r1;
    }
    __syncthreads();

    uint32_t ab0 = s2u(Ab), ab1 = s2u(Ab + 512);
    for (int cc = 0; cc < NCH; cc++) {
        bool more = (cc + 1 < NCH);
        if (more) loadA<DEC>(r0, r1, cc + 1, xrow, hrow, vrow, quad);
        uint32_t ab = (cc & 1) ? ab1 : ab0;
        #pragma unroll
        for (int s4 = 0; s4 < 4; s4++) {
            int ccol = (2 * s4 + halfsel) ^ (arow & 7);
            uint32_t addr = ab + (uint32_t)((arow * 8 + ccol) * 16);
            uint32_t q0, q1, q2, q3;
            asm volatile("ldmatrix.sync.aligned.m8n8.x4.shared.b16 {%0,%1,%2,%3}, [%4];"
                         : "=r"(q0), "=r"(q1), "=r"(q2), "=r"(q3) : "r"(addr));
            uint32_t a0 = f2tf32(q0), a1 = f2tf32(q1), a2 = f2tf32(q2), a3 = f2tf32(q3);
            float4 wv = Wp[((size_t)wn * KS + (cc * 4 + s4)) * 32 + l];
            mma8(acc[0], a0, a1, a2, a3, __float_as_uint(wv.x), __float_as_uint(wv.y));
            mma8(acc[1], a0, a1, a2, a3, __float_as_uint(wv.z), __float_as_uint(wv.w));
        }
        if (more) {
            float4* Bn = (cc & 1) ? Ab : (Ab + 512);
            int c0 = quad * 2;
            Bn[mrow * 8 + (c0 ^ (mrow & 7))] = r0;
            Bn[mrow * 8 + ((c0 + 1) ^ (mrow & 7))] = r1;
        }
        __syncthreads();
    }

    // ---- cell epilogue: reassemble i,f,g,o via shfl_xor(1) ----
    bool evn = ((t0 & 1) == 0);
    #pragma unroll
    for (int hh = 0; hh < 2; hh++) {
        float d0 = acc[hh][0], d1 = acc[hh][1], d2 = acc[hh][2], d3 = acc[hh][3];
        float x0 = __shfl_xor_sync(0xffffffffu, d0, 1);
        float x1 = __shfl_xor_sync(0xffffffffu, d1, 1);
        float x2 = __shfl_xor_sync(0xffffffffu, d2, 1);
        float x3 = __shfl_xor_sync(0xffffffffu, d3, 1);
        int j = nb * 8 + wn * 4 + hh * 2 + (t0 >> 1);
        int b = m16 + gid + (evn ? 0 : 8);
        float gi = (evn ? d0 : x2) + bias[hh][0];
        float gf = (evn ? d1 : x3) + bias[hh][1];
        float gg = (evn ? x0 : d2) + bias[hh][2];
        float go = (evn ? x1 : d3) + bias[hh][3];
        float c  = g_c[b * Hz + j];
        float cn = sigm(gf) * c + sigm(gi) * tanhf(gg);
        float hn = sigm(go) * tanhf(cn);
        g_c[b * Hz + j] = cn;
        hout[b * Hz + j] = hn;
        if (!DEC)
            g_enc[((size_t)b * LCz + t) * Hz + j] = __float2bfloat16(hn);
    }
}

__device__ __forceinline__ void load_bias(float bias[2][4],
    const float* __restrict__ bih, const float* __restrict__ bhh, int nb)
{
    int l = threadIdx.x & 31;
    int wn = (threadIdx.x >> 5) >> 2;
    int t0 = l & 3;
    #pragma unroll
    for (int hh = 0; hh < 2; hh++) {
        int j = nb * 8 + wn * 4 + hh * 2 + (t0 >> 1);
        #pragma unroll
        for (int g4 = 0; g4 < 4; g4++)
            bias[hh][g4] = bih[g4 * Hz + j] + bhh[g4 * Hz + j];
    }
}

// ---------------- scalar GEMM segment (P2/P4, unchanged from R4) ------------
__device__ __forceinline__ void seg_accum(
    const float* __restrict__ A, int lda,
    const float* __restrict__ W, int ldw, int K,
    float acc[2][4], float* sm)
{
    float (*As)[32] = (float (*)[32])sm;
    float (*Ws)[64] = (float (*)[64])(sm + 512);
    int tid = threadIdx.x;
    int cg = tid & 15, bg = tid >> 4;
    int ar = tid >> 2, k4 = tid & 3;
    int wr = tid >> 2;
    const float* wpt = W + (size_t)wr * ldw + k4 * 4;
    const float* apt = A + (size_t)(tid < 128 ? ar : 0) * lda + k4 * 4;
    for (int k0 = 0; k0 < K; k0 += 16) {
        if (tid < 128) {
            float4 av = *(const float4*)(apt + k0);
            As[k4 * 4 + 0][ar] = av.x;
            As[k4 * 4 + 1][ar] = av.y;
            As[k4 * 4 + 2][ar] = av.z;
            As[k4 * 4 + 3][ar] = av.w;
        }
        {
            float4 wv = *(const float4*)(wpt + k0);
            Ws[k4 * 4 + 0][wr] = wv.x;
            Ws[k4 * 4 + 1][wr] = wv.y;
            Ws[k4 * 4 + 2][wr] = wv.z;
            Ws[k4 * 4 + 3][wr] = wv.w;
        }
        __syncthreads();
        #pragma unroll
        for (int kk = 0; kk < 16; kk++) {
            float a0 = As[kk][bg * 2];
            float a1 = As[kk][bg * 2 + 1];
            float4 wv = *(const float4*)&Ws[kk][cg * 4];
            acc[0][0] += a0 * wv.x; acc[0][1] += a0 * wv.y; acc[0][2] += a0 * wv.z; acc[0][3] += a0 * wv.w;
            acc[1][0] += a1 * wv.x; acc[1][1] += a1 * wv.y; acc[1][2] += a1 * wv.z; acc[1][3] += a1 * wv.w;
        }
        __syncthreads();
    }
}

__device__ __forceinline__ void plain_epi(
    float acc[2][4], float* __restrict__ outp, int m0, int n0,
    const float* __restrict__ bias)
{
    int tid = threadIdx.x, cg = tid & 15, bg = tid >> 4;
    #pragma unroll
    for (int r = 0; r < 2; r++) {
        int b = m0 + bg * 2 + r;
        #pragma unroll
        for (int i = 0; i < 4; i++) {
            int n = n0 + cg * 4 + i;
            float v = acc[r][i];
            if (bias) v += bias[n];
            outp[b * Hz + n] = v;
        }
    }
}

// ---------------- per-batch attention (unchanged from R4) -------------------
__device__ void attn_block(int b, const int* __restrict__ C_pad, float* sm)
{
    float* sq  = sm;
    float* ss  = sm + 512;
    float* red = sm + 1024;
    float* sca = sm + 1040;
    int tid = threadIdx.x, lane = tid & 31, w = tid >> 5;

    const float* qp = (const float*)g_qp;
    for (int i = tid; i < Hz; i += 256)
        sq[i] = qp[b * Hz + i] + qp[BHS + b * Hz + i]
              + qp[2 * BHS + b * Hz + i] + qp[3 * BHS + b * Hz + i];
    __syncthreads();

    float qreg[16];
    #pragma unroll
    for (int i = 0; i < 16; i++) qreg[i] = sq[lane * 16 + i];

    const __nv_bfloat16* eb = g_enc + (size_t)b * LCz * Hz;
    for (int l = w; l < LCz; l += 8) {
        float sc = -INFINITY;
        if (C_pad[b * LCz + l] == 0) {
            const __nv_bfloat16* row = eb + (size_t)l * Hz + lane * 16;
            uint4 u0 = *(const uint4*)row;
            uint4 u1 = *(const uint4*)(row + 8);
            const __nv_bfloat162* h0 = (const __nv_bfloat162*)&u0;
            const __nv_bfloat162* h1 = (const __nv_bfloat162*)&u1;
            float acc = 0.f;
            #pragma unroll
            for (int i = 0; i < 4; i++) {
                float2 f0 = __bfloat1622float2(h0[i]);
                float2 f1 = __bfloat1622float2(h1[i]);
                acc += f0.x * qreg[2 * i]     + f0.y * qreg[2 * i + 1];
                acc += f1.x * qreg[8 + 2 * i] + f1.y * qreg[8 + 2 * i + 1];
            }
            #pragma unroll
            for (int o = 16; o > 0; o >>= 1) acc += __shfl_xor_sync(0xffffffffu, acc, o);
            sc = acc;
        }
        if (lane == 0) ss[l] = sc;
    }
    __syncthreads();

    float m = -INFINITY;
    for (int l = tid; l < LCz; l += 256) m = fmaxf(m, ss[l]);
    #pragma unroll
    for (int o = 16; o > 0; o >>= 1) m = fmaxf(m, __shfl_xor_sync(0xffffffffu, m, o));
    if (lane == 0) red[w] = m;
    __syncthreads();
    if (tid == 0) {
        float mm = red[0];
        for (int i = 1; i < 8; i++) mm = fmaxf(mm, red[i]);
        sca[0] = mm;
    }
    __syncthreads();
    float bmax = sca[0];

    float s = 0.f;
    for (int l = tid; l < LCz; l += 256) {
        float v = ss[l];
        float e = (v == -INFINITY) ? 0.f : expf(v - bmax);
        ss[l] = e;
        s += e;
    }
    #pragma unroll
    for (int o = 16; o > 0; o >>= 1) s += __shfl_xor_sync(0xffffffffu, s, o);
    if (lane == 0) red[w] = s;
    __syncthreads();
    if (tid == 0) {
        float t2 = 0.f;
        for (int i = 0; i < 8; i++) t2 += red[i];
        sca[1] = t2;
    }
    __syncthreads();
    float inv = 1.f / sca[1];

    float a0 = 0.f, a1 = 0.f;
    for (int l = 0; l < LCz; l++) {
        float d = ss[l];
        if (d == 0.f) continue;
        __nv_bfloat162 p = *(const __nv_bfloat162*)(eb + (size_t)l * Hz + 2 * tid);
        float2 f = __bfloat1622float2(p);
        a0 += d * f.x;
        a1 += d * f.y;
    }
    g_attn[b * Hz + 2 * tid]     = a0 * inv;
    g_attn[b * Hz + 2 * tid + 1] = a1 * inv;
}

// ---------------- per-batch logits + masked CE (unchanged) ------------------
__device__ void logits_ce(int b, int tt, const int* __restrict__ E,
                          const float* __restrict__ voc_W,
                          const float* __restrict__ voc_b, float* sm)
{
    float* st = sm;
    float* sl = sm + 512;
    int tid = threadIdx.x, lane = tid & 31, w = tid >> 5;
    __syncthreads();

    const float* vp = (const float*)g_vp;
    for (int i = tid; i < Hz; i += 256) {
        float v = vp[b * Hz + i] + vp[BHS + b * Hz + i]
                + vp[2 * BHS + b * Hz + i] + vp[3 * BHS + b * Hz + i];
        st[i] = tanhf(v);
    }
    __syncthreads();

    float sreg[16];
    #pragma unroll
    for (int i = 0; i < 16; i++) sreg[i] = st[lane * 16 + i];

    for (int v = w; v < Vz; v += 8) {
        const float* wr = voc_W + (size_t)v * Hz + lane * 16;
        float acc = 0.f;
        #pragma unroll
        for (int i = 0; i < 16; i += 4) {
            float4 x = *(const float4*)(wr + i);
            acc += x.x * sreg[i] + x.y * sreg[i + 1] + x.z * sreg[i + 2] + x.w * sreg[i + 3];
        }
        #pragma unroll
        for (int o = 16; o > 0; o >>= 1) acc += __shfl_xor_sync(0xffffffffu, acc, o);
        if (lane == 0) sl[v] = acc + voc_b[v];
    }
    __syncthreads();

    if (w == 0) {
        float m = -INFINITY;
        for (int v = lane; v < Vz; v += 32) m = fmaxf(m, sl[v]);
        #pragma unroll
        for (int o = 16; o > 0; o >>= 1) m = fmaxf(m, __shfl_xor_sync(0xffffffffu, m, o));
        float s = 0.f;
        for (int v = lane; v < Vz; v += 32) s += expf(sl[v] - m);
        #pragma unroll
        for (int o = 16; o > 0; o >>= 1) s += __shfl_xor_sync(0xffffffffu, s, o);
        if (lane == 0) {
            int tv = E[b * LEz + tt + 1];
            int idx = b * TDEC + tt;
            if (tv != 0) { g_nll[idx] = m + logf(s) - sl[tv]; g_msk[idx] = 1.f; }
            else         { g_nll[idx] = 0.f;                  g_msk[idx] = 0.f; }
        }
    }
}

// ---------------- the single persistent kernel ------------------------------
__global__ void __launch_bounds__(256, 1) persist_kernel(
    const float* __restrict__ C,       const int* __restrict__ C_pad,
    const int* __restrict__ E,         const float* __restrict__ E_emb,
    const float* __restrict__ enc_Wih, const float* __restrict__ enc_Whh,
    const float* __restrict__ enc_bih, const float* __restrict__ enc_bhh,
    const float* __restrict__ dec_Wih, const float* __restrict__ dec_Whh,
    const float* __restrict__ dec_bih, const float* __restrict__ dec_bhh,
    const float* __restrict__ att_W,   const float* __restrict__ out_W,
    const float* __restrict__ out_b,   const float* __restrict__ voc_W,
    const float* __restrict__ voc_b,   float* __restrict__ out)
{
    extern __shared__ __align__(16) float4 dsm[];
    float4* Wp  = dsm;
    float4* Ab  = dsm + 9216;
    float*  scr = (float*)(dsm + 10240);

    int bid = blockIdx.x, tid = threadIdx.x;
    int lane = tid & 31, w = tid >> 5;
    int mh = bid & 1, nb = bid >> 1;

    // ---- init state ----
    for (int i = bid * 256 + tid; i < BHS; i += NBLK * 256) { g_h[0][i] = 0.f; g_c[i] = 0.f; }
    float* vpf = (float*)g_vp;
    for (int i = bid * 256 + tid; i < 4 * BHS; i += NBLK * 256) vpf[i] = 0.f;
    gsync();

    // ---- encoder ----
    pack_W(Wp, nb, 80, Vz, enc_Wih, Vz, enc_Whh, Hz);
    __syncthreads();
    float biasE[2][4];
    load_bias(biasE, enc_bih, enc_bhh, nb);
    for (int t = 0; t < LCz; t++) {
        const float* hin = g_h[t & 1];
        float* hout = g_h[1 - (t & 1)];
        gates_step<false>(Wp, Ab, C, t, hin, hout, mh, nb, biasE);
        gsync();
    }

    // ---- decoder ----
    pack_W(Wp, nb, 144, Vz + Hz, dec_Wih, Vz + Hz, dec_Whh, Hz);
    __syncthreads();
    float biasD[2][4];
    load_bias(biasD, dec_bih, dec_bhh, nb);

    int ks = bid & 3, kr = bid >> 2;
    int km0 = (kr & 3) * 32, kn0 = (kr >> 2) * 64;
    for (int t = 0; t < TDEC; t++) {
        const float* hin = g_h[t & 1];
        float* hout = g_h[1 - (t & 1)];

        // P1: gates (tf32 mma) + cell
        gates_step<true>(Wp, Ab, E_emb, t, hin, hout, mh, nb, biasD);
        gsync();

        // P2: q partials (K-split x4)
        {
            float acc[2][4] = {};
            seg_accum(hout + km0 * Hz + ks * 128, Hz,
                      att_W + (size_t)kn0 * Hz + ks * 128, Hz, 128, acc, scr);
            plain_epi(acc, g_qp[ks], km0, kn0, nullptr);
        }
        gsync();

        // P3: attention for batch=bid + logits/CE of step t-1
        attn_block(bid, C_pad, scr);
        if (t > 0) logits_ce(bid, t - 1, E, voc_W, voc_b, scr);
        gsync();

        // P4: out-proj partials (K-split x4); bias folded into split 0
        {
            const float* Asrc = (ks < 2) ? hout : g_attn;
            int koff = (ks & 1) * 256;
            float acc[2][4] = {};
            seg_accum(Asrc + km0 * Hz + koff, Hz,
                      out_W + (size_t)kn0 * (2 * Hz) + ks * 256, 2 * Hz, 256, acc, scr);
            plain_epi(acc, g_vp[ks], km0, kn0, (ks == 0) ? out_b : nullptr);
        }
        gsync();
    }

    // ---- last step's logits/CE ----
    logits_ce(bid, TDEC - 1, E, voc_W, voc_b, scr);
    gsync();

    // ---- deterministic reduction ----
    {
        float s = 0.f, c = 0.f;
        for (int i = tid; i < TDEC; i += 256) {
            s += g_nll[bid * TDEC + i];
            c += g_msk[bid * TDEC + i];
        }
        #pragma unroll
        for (int o = 16; o > 0; o >>= 1) {
            s += __shfl_xor_sync(0xffffffffu, s, o);
            c += __shfl_xor_sync(0xffffffffu, c, o);
        }
        __syncthreads();
        if (lane == 0) { scr[w] = s; scr[8 + w] = c; }
        __syncthreads();
        if (tid == 0) {
            float ts = 0.f, tc = 0.f;
            for (int i = 0; i < 8; i++) { ts += scr[i]; tc += scr[8 + i]; }
            g_ps[bid] = ts; g_pc[bid] = tc;
        }
    }
    gsync();
    if (bid == 0 && tid == 0) {
        float ts = 0.f, tc = 0.f;
        for (int i = 0; i < NBLK; i++) { ts += g_ps[i]; tc += g_pc[i]; }
        out[0] = ts / fmaxf(tc, 1.f);
    }
}

// ---------------- host entry (single launch => 1-node graph) ----------------
extern "C" void kernel_launch(void* const* d_in, const int* in_sizes, int n_in,
                              void* d_out, int out_size)
{
    cudaFuncSetAttribute((const void*)persist_kernel,
                         cudaFuncAttributeMaxDynamicSharedMemorySize, SMEM_BYTES);
    persist_kernel<<<NBLK, 256, SMEM_BYTES>>>(
        (const float*)d_in[0],  (const int*)d_in[1],
        (const int*)d_in[2],    (const float*)d_in[3],
        (const float*)d_in[4],  (const float*)d_in[5],
        (const float*)d_in[6],  (const float*)d_in[7],
        (const float*)d_in[8],  (const float*)d_in[9],
        (const float*)d_in[10], (const float*)d_in[11],
        (const float*)d_in[12], (const float*)d_in[13],
        (const float*)d_in[14], (const float*)d_in[15],
        (const float*)d_in[16], (float*)d_out);
}

// round 6
// speedup vs baseline: 1.5932x; 1.1841x over previous
#include <cuda_runtime.h>
#include <cuda_bf16.h>
#include <math.h>
#include <stdint.h>

#define Bz   128
#define LCz  512
#define LEz  512
#define Hz   512
#define Vz   128
#define TDEC 511
#define NBLK 128
#define BHS  (Bz * Hz)   // 65536

// dynamic smem layout (float4 units):
//   Wp  [0,     9216)  : W fragment pack (2 wn * 144 ksteps * 32 lanes)
//   Ab  [9216, 10240)  : A staging, 2 buffers of 64x8 float4
//   scr [10240, ...)   : 6144 floats generic scratch (attn needs 5136)
#define SMEM_BYTES 188416

// ---------------- static device scratch -------------------------------------
__device__ __align__(16) float g_h[2][BHS];
__device__ __align__(16) float g_c[BHS];
__device__ __align__(16) float g_vp[4][BHS];   // V partials (K-split out-proj)
__device__ __align__(16) float g_qp[4][BHS];   // q partials (K-split att-proj)
__device__ __align__(16) float g_attn[BHS];
__device__ __align__(16) __nv_bfloat16 g_enc[(size_t)Bz * LCz * Hz];  // 67 MB
__device__ float g_nll[Bz * TDEC];
__device__ float g_msk[Bz * TDEC];
__device__ float g_ps[NBLK], g_pc[NBLK];
__device__ unsigned g_arrive;
__device__ volatile unsigned g_gen;

__device__ __forceinline__ float sigm(float x) { return 1.f / (1.f + expf(-x)); }

__device__ __forceinline__ uint32_t s2u(const void* p) {
    return (uint32_t)__cvta_generic_to_shared(p);
}
__device__ __forceinline__ uint32_t f2tf32(uint32_t raw) {
    uint32_t u;
    float x = __uint_as_float(raw);
    asm("cvt.rna.tf32.f32 %0, %1;" : "=r"(u) : "f"(x));
    return u;
}
__device__ __forceinline__ void mma8(float acc[4],
    uint32_t a0, uint32_t a1, uint32_t a2, uint32_t a3,
    uint32_t b0, uint32_t b1)
{
    asm volatile("mma.sync.aligned.m16n8k8.row.col.f32.tf32.tf32.f32 "
        "{%0,%1,%2,%3},{%4,%5,%6,%7},{%8,%9},{%0,%1,%2,%3};"
        : "+f"(acc[0]), "+f"(acc[1]), "+f"(acc[2]), "+f"(acc[3])
        : "r"(a0), "r"(a1), "r"(a2), "r"(a3), "r"(b0), "r"(b1));
}

// ---------------- software grid barrier -------------------------------------
__device__ __forceinline__ void gsync() {
    __syncthreads();
    if (threadIdx.x == 0) {
        __threadfence();
        unsigned gen = g_gen;
        if (atomicAdd(&g_arrive, 1u) == NBLK - 1u) {
            g_arrive = 0u;
            __threadfence();
            g_gen = gen + 1u;
        } else {
            while (g_gen == gen) __nanosleep(32);
        }
        __threadfence();
    }
    __syncthreads();
}

// ---------------- W fragment pack (once per phase) --------------------------
__device__ void pack_W(float4* Wp, int nb, int KS, int Kih,
                       const float* __restrict__ Wih, int ldih,
                       const float* __restrict__ Whh, int ldhh)
{
    for (int idx = threadIdx.x; idx < 2 * KS * 32; idx += 256) {
        int wn  = idx / (KS * 32);
        int rem = idx - wn * (KS * 32);
        int s = rem >> 5, l = rem & 31;
        int gid = l >> 2, tig = l & 3;
        int k0 = s * 8 + tig, k1 = k0 + 4;
        float v[4];
        #pragma unroll
        for (int hh = 0; hh < 2; hh++) {
            int c = hh * 8 + gid;
            int jj = wn * 4 + (c >> 2);
            int gate = c & 3;
            int grow = gate * Hz + nb * 8 + jj;
            const float* pi = Wih + (size_t)grow * ldih;
            const float* ph = Whh + (size_t)grow * ldhh;
            v[hh * 2]     = (k0 < Kih) ? pi[k0] : ph[k0 - Kih];
            v[hh * 2 + 1] = (k1 < Kih) ? pi[k1] : ph[k1 - Kih];
        }
        float4 o;
        o.x = __uint_as_float(f2tf32(__float_as_uint(v[0])));
        o.y = __uint_as_float(f2tf32(__float_as_uint(v[1])));
        o.z = __uint_as_float(f2tf32(__float_as_uint(v[2])));
        o.w = __uint_as_float(f2tf32(__float_as_uint(v[3])));
        Wp[idx] = o;
    }
}

// ---------------- A chunk loader (2 float4 per thread) ----------------------
template<bool DEC>
__device__ __forceinline__ void loadA(float4& r0, float4& r1, int cc,
    const float* __restrict__ xrow, const float* __restrict__ hrow,
    const float* __restrict__ vrow, int quad)
{
    #pragma unroll
    for (int u = 0; u < 2; u++) {
        int kf4 = cc * 8 + quad * 2 + u;
        float4 v;
        if (DEC) {
            if (kf4 < 32) {
                v = *(const float4*)(xrow + kf4 * 4);
            } else if (kf4 < 160) {
                int off = kf4 * 4 - 128;
                float4 a = *(const float4*)(vrow + off);
                float4 b = *(const float4*)(vrow + off + BHS);
                float4 c = *(const float4*)(vrow + off + 2 * BHS);
                float4 d = *(const float4*)(vrow + off + 3 * BHS);
                v.x = a.x + b.x + c.x + d.x;
                v.y = a.y + b.y + c.y + d.y;
                v.z = a.z + b.z + c.z + d.z;
                v.w = a.w + b.w + c.w + d.w;
            } else {
                v = *(const float4*)(hrow + kf4 * 4 - 640);
            }
        } else {
            if (kf4 < 32) v = *(const float4*)(xrow + kf4 * 4);
            else          v = *(const float4*)(hrow + kf4 * 4 - 128);
        }
        if (u == 0) r0 = v; else r1 = v;
    }
}

// ---------------- fused gates GEMM (tf32 mma) + LSTM cell -------------------
template<bool DEC>
__device__ __forceinline__ void gates_step(
    const float4* __restrict__ Wp, float4* __restrict__ Ab,
    const float* __restrict__ xbase, int t,
    const float* __restrict__ hin, float* __restrict__ hout,
    int mh, int nb, const float bias[2][4])
{
    const int NCH = DEC ? 36 : 20;
    const int KS  = DEC ? 144 : 80;
    int tid = threadIdx.x;
    int l = tid & 31, wrp = tid >> 5;
    int wm = wrp & 3, wn = wrp >> 2;
    int gid = l >> 2, t0 = l & 3;
    int quad = tid & 3, mrow = tid >> 2;
    int m16 = mh * 64 + wm * 16;
    int arow = wm * 16 + ((l >> 3) & 1) * 8 + (l & 7);
    int halfsel = l >> 4;

    int bS = mh * 64 + mrow;
    const float* xrow = xbase + ((size_t)bS * (DEC ? LEz : LCz) + t) * Vz;
    const float* hrow = hin + bS * Hz;
    const float* vrow = (const float*)g_vp + bS * Hz;

    float acc[2][4];
    #pragma unroll
    for (int i = 0; i < 2; i++)
        #pragma unroll
        for (int k = 0; k < 4; k++) acc[i][k] = 0.f;

    float4 r0, r1;
    loadA<DEC>(r0, r1, 0, xrow, hrow, vrow, quad);
    {
        int c0 = quad * 2;
        Ab[mrow * 8 + (c0 ^ (mrow & 7))] = r0;
        Ab[mrow * 8 + ((c0 + 1) ^ (mrow & 7))] = r1;
    }
    __syncthreads();

    uint32_t ab0 = s2u(Ab), ab1 = s2u(Ab + 512);
    for (int cc = 0; cc < NCH; cc++) {
        bool more = (cc + 1 < NCH);
        if (more) loadA<DEC>(r0, r1, cc + 1, xrow, hrow, vrow, quad);
        uint32_t ab = (cc & 1) ? ab1 : ab0;
        #pragma unroll
        for (int s4 = 0; s4 < 4; s4++) {
            int ccol = (2 * s4 + halfsel) ^ (arow & 7);
            uint32_t addr = ab + (uint32_t)((arow * 8 + ccol) * 16);
            uint32_t q0, q1, q2, q3;
            asm volatile("ldmatrix.sync.aligned.m8n8.x4.shared.b16 {%0,%1,%2,%3}, [%4];"
                         : "=r"(q0), "=r"(q1), "=r"(q2), "=r"(q3) : "r"(addr));
            uint32_t a0 = f2tf32(q0), a1 = f2tf32(q1), a2 = f2tf32(q2), a3 = f2tf32(q3);
            float4 wv = Wp[((size_t)wn * KS + (cc * 4 + s4)) * 32 + l];
            mma8(acc[0], a0, a1, a2, a3, __float_as_uint(wv.x), __float_as_uint(wv.y));
            mma8(acc[1], a0, a1, a2, a3, __float_as_uint(wv.z), __float_as_uint(wv.w));
        }
        if (more) {
            float4* Bn = (cc & 1) ? Ab : (Ab + 512);
            int c0 = quad * 2;
            Bn[mrow * 8 + (c0 ^ (mrow & 7))] = r0;
            Bn[mrow * 8 + ((c0 + 1) ^ (mrow & 7))] = r1;
        }
        __syncthreads();
    }

    bool evn = ((t0 & 1) == 0);
    #pragma unroll
    for (int hh = 0; hh < 2; hh++) {
        float d0 = acc[hh][0], d1 = acc[hh][1], d2 = acc[hh][2], d3 = acc[hh][3];
        float x0 = __shfl_xor_sync(0xffffffffu, d0, 1);
        float x1 = __shfl_xor_sync(0xffffffffu, d1, 1);
        float x2 = __shfl_xor_sync(0xffffffffu, d2, 1);
        float x3 = __shfl_xor_sync(0xffffffffu, d3, 1);
        int j = nb * 8 + wn * 4 + hh * 2 + (t0 >> 1);
        int b = m16 + gid + (evn ? 0 : 8);
        float gi = (evn ? d0 : x2) + bias[hh][0];
        float gf = (evn ? d1 : x3) + bias[hh][1];
        float gg = (evn ? x0 : d2) + bias[hh][2];
        float go = (evn ? x1 : d3) + bias[hh][3];
        float c  = g_c[b * Hz + j];
        float cn = sigm(gf) * c + sigm(gi) * tanhf(gg);
        float hn = sigm(go) * tanhf(cn);
        g_c[b * Hz + j] = cn;
        hout[b * Hz + j] = hn;
        if (!DEC)
            g_enc[((size_t)b * LCz + t) * Hz + j] = __float2bfloat16(hn);
    }
}

__device__ __forceinline__ void load_bias(float bias[2][4],
    const float* __restrict__ bih, const float* __restrict__ bhh, int nb)
{
    int l = threadIdx.x & 31;
    int wn = (threadIdx.x >> 5) >> 2;
    int t0 = l & 3;
    #pragma unroll
    for (int hh = 0; hh < 2; hh++) {
        int j = nb * 8 + wn * 4 + hh * 2 + (t0 >> 1);
        #pragma unroll
        for (int g4 = 0; g4 < 4; g4++)
            bias[hh][g4] = bih[g4 * Hz + j] + bhh[g4 * Hz + j];
    }
}

// ---------------- scalar GEMM segment (P2/P4) -------------------------------
__device__ __forceinline__ void seg_accum(
    const float* __restrict__ A, int lda,
    const float* __restrict__ W, int ldw, int K,
    float acc[2][4], float* sm)
{
    float (*As)[32] = (float (*)[32])sm;
    float (*Ws)[64] = (float (*)[64])(sm + 512);
    int tid = threadIdx.x;
    int cg = tid & 15, bg = tid >> 4;
    int ar = tid >> 2, k4 = tid & 3;
    int wr = tid >> 2;
    const float* wpt = W + (size_t)wr * ldw + k4 * 4;
    const float* apt = A + (size_t)(tid < 128 ? ar : 0) * lda + k4 * 4;
    for (int k0 = 0; k0 < K; k0 += 16) {
        if (tid < 128) {
            float4 av = *(const float4*)(apt + k0);
            As[k4 * 4 + 0][ar] = av.x;
            As[k4 * 4 + 1][ar] = av.y;
            As[k4 * 4 + 2][ar] = av.z;
            As[k4 * 4 + 3][ar] = av.w;
        }
        {
            float4 wv = *(const float4*)(wpt + k0);
            Ws[k4 * 4 + 0][wr] = wv.x;
            Ws[k4 * 4 + 1][wr] = wv.y;
            Ws[k4 * 4 + 2][wr] = wv.z;
            Ws[k4 * 4 + 3][wr] = wv.w;
        }
        __syncthreads();
        #pragma unroll
        for (int kk = 0; kk < 16; kk++) {
            float a0 = As[kk][bg * 2];
            float a1 = As[kk][bg * 2 + 1];
            float4 wv = *(const float4*)&Ws[kk][cg * 4];
            acc[0][0] += a0 * wv.x; acc[0][1] += a0 * wv.y; acc[0][2] += a0 * wv.z; acc[0][3] += a0 * wv.w;
            acc[1][0] += a1 * wv.x; acc[1][1] += a1 * wv.y; acc[1][2] += a1 * wv.z; acc[1][3] += a1 * wv.w;
        }
        __syncthreads();
    }
}

__device__ __forceinline__ void plain_epi(
    float acc[2][4], float* __restrict__ outp, int m0, int n0,
    const float* __restrict__ bias)
{
    int tid = threadIdx.x, cg = tid & 15, bg = tid >> 4;
    #pragma unroll
    for (int r = 0; r < 2; r++) {
        int b = m0 + bg * 2 + r;
        #pragma unroll
        for (int i = 0; i < 4; i++) {
            int n = n0 + cg * 4 + i;
            float v = acc[r][i];
            if (bias) v += bias[n];
            outp[b * Hz + n] = v;
        }
    }
}

// ---------------- per-batch attention: branch-free, warp-parallel -----------
__device__ void attn_block(int b, const int* __restrict__ C_pad, float* sm)
{
    float* sq   = sm;          // 512
    float* ss   = sm + 512;    // 512
    float* red  = sm + 1024;   // 8
    float* sca  = sm + 1032;   // 2
    float* wacc = sm + 1040;   // 8 * 512 warp partials
    int tid = threadIdx.x, lane = tid & 31, w = tid >> 5;

    const float* qp = (const float*)g_qp;
    for (int i = tid; i < Hz; i += 256)
        sq[i] = qp[b * Hz + i] + qp[BHS + b * Hz + i]
              + qp[2 * BHS + b * Hz + i] + qp[3 * BHS + b * Hz + i];
    __syncthreads();

    float qreg[16];
    #pragma unroll
    for (int i = 0; i < 16; i++) qreg[i] = sq[lane * 16 + i];

    const __nv_bfloat16* eb = g_enc + (size_t)b * LCz * Hz;

    // pass 1: scores — unconditional loads, mask after the dot
    #pragma unroll 4
    for (int l = w; l < LCz; l += 8) {
        const __nv_bfloat16* row = eb + (size_t)l * Hz + lane * 16;
        uint4 u0 = *(const uint4*)row;
        uint4 u1 = *(const uint4*)(row + 8);
        const __nv_bfloat162* h0 = (const __nv_bfloat162*)&u0;
        const __nv_bfloat162* h1 = (const __nv_bfloat162*)&u1;
        float acc = 0.f;
        #pragma unroll
        for (int i = 0; i < 4; i++) {
            float2 f0 = __bfloat1622float2(h0[i]);
            float2 f1 = __bfloat1622float2(h1[i]);
            acc += f0.x * qreg[2 * i]     + f0.y * qreg[2 * i + 1];
            acc += f1.x * qreg[8 + 2 * i] + f1.y * qreg[8 + 2 * i + 1];
        }
        #pragma unroll
        for (int o = 16; o > 0; o >>= 1) acc += __shfl_xor_sync(0xffffffffu, acc, o);
        if (lane == 0)
            ss[l] = (C_pad[b * LCz + l] != 0) ? -INFINITY : acc;
    }
    __syncthreads();

    // block max
    float m = -INFINITY;
    for (int l = tid; l < LCz; l += 256) m = fmaxf(m, ss[l]);
    #pragma unroll
    for (int o = 16; o > 0; o >>= 1) m = fmaxf(m, __shfl_xor_sync(0xffffffffu, m, o));
    if (lane == 0) red[w] = m;
    __syncthreads();
    if (tid == 0) {
        float mm = red[0];
        for (int i = 1; i < 8; i++) mm = fmaxf(mm, red[i]);
        sca[0] = mm;
    }
    __syncthreads();
    float bmax = sca[0];

    // exp + sum
    float s = 0.f;
    for (int l = tid; l < LCz; l += 256) {
        float v = ss[l];
        float e = (v == -INFINITY) ? 0.f : expf(v - bmax);
        ss[l] = e;
        s += e;
    }
    #pragma unroll
    for (int o = 16; o > 0; o >>= 1) s += __shfl_xor_sync(0xffffffffu, s, o);
    if (lane == 0) red[w] = s;
    __syncthreads();
    if (tid == 0) {
        float t2 = 0.f;
        for (int i = 0; i < 8; i++) t2 += red[i];
        sca[1] = t2;
    }
    __syncthreads();
    float inv = 1.f / sca[1];

    // pass 2: warp-parallel weighted sum, register accumulation
    float acc2[16];
    #pragma unroll
    for (int i = 0; i < 16; i++) acc2[i] = 0.f;
    #pragma unroll 4
    for (int l = w; l < LCz; l += 8) {
        float d = ss[l];                  // 0 for padded rows — exact
        const __nv_bfloat16* row = eb + (size_t)l * Hz + lane * 16;
        uint4 u0 = *(const uint4*)row;
        uint4 u1 = *(const uint4*)(row + 8);
        const __nv_bfloat162* h0 = (const __nv_bfloat162*)&u0;
        const __nv_bfloat162* h1 = (const __nv_bfloat162*)&u1;
        #pragma unroll
        for (int i = 0; i < 4; i++) {
            float2 f0 = __bfloat1622float2(h0[i]);
            float2 f1 = __bfloat1622float2(h1[i]);
            acc2[2 * i]         += d * f0.x;
            acc2[2 * i + 1]     += d * f0.y;
            acc2[8 + 2 * i]     += d * f1.x;
            acc2[8 + 2 * i + 1] += d * f1.y;
        }
    }
    #pragma unroll
    for (int i = 0; i < 16; i++) wacc[w * Hz + lane * 16 + i] = acc2[i];
    __syncthreads();

    // cross-warp reduce: each thread owns 2 h positions
    for (int h = tid; h < Hz; h += 256) {
        float t2 = 0.f;
        #pragma unroll
        for (int ww = 0; ww < 8; ww++) t2 += wacc[ww * Hz + h];
        g_attn[b * Hz + h] = t2 * inv;
    }
}

// ---------------- per-batch logits + masked CE ------------------------------
__device__ void logits_ce(int b, int tt, const int* __restrict__ E,
                          const float* __restrict__ voc_W,
                          const float* __restrict__ voc_b, float* sm)
{
    float* st = sm;
    float* sl = sm + 512;
    int tid = threadIdx.x, lane = tid & 31, w = tid >> 5;
    __syncthreads();

    const float* vp = (const float*)g_vp;
    for (int i = tid; i < Hz; i += 256) {
        float v = vp[b * Hz + i] + vp[BHS + b * Hz + i]
                + vp[2 * BHS + b * Hz + i] + vp[3 * BHS + b * Hz + i];
        st[i] = tanhf(v);
    }
    __syncthreads();

    float sreg[16];
    #pragma unroll
    for (int i = 0; i < 16; i++) sreg[i] = st[lane * 16 + i];

    for (int v = w; v < Vz; v += 8) {
        const float* wr = voc_W + (size_t)v * Hz + lane * 16;
        float acc = 0.f;
        #pragma unroll
        for (int i = 0; i < 16; i += 4) {
            float4 x = *(const float4*)(wr + i);
            acc += x.x * sreg[i] + x.y * sreg[i + 1] + x.z * sreg[i + 2] + x.w * sreg[i + 3];
        }
        #pragma unroll
        for (int o = 16; o > 0; o >>= 1) acc += __shfl_xor_sync(0xffffffffu, acc, o);
        if (lane == 0) sl[v] = acc + voc_b[v];
    }
    __syncthreads();

    if (w == 0) {
        float m = -INFINITY;
        for (int v = lane; v < Vz; v += 32) m = fmaxf(m, sl[v]);
        #pragma unroll
        for (int o = 16; o > 0; o >>= 1) m = fmaxf(m, __shfl_xor_sync(0xffffffffu, m, o));
        float s = 0.f;
        for (int v = lane; v < Vz; v += 32) s += expf(sl[v] - m);
        #pragma unroll
        for (int o = 16; o > 0; o >>= 1) s += __shfl_xor_sync(0xffffffffu, s, o);
        if (lane == 0) {
            int tv = E[b * LEz + tt + 1];
            int idx = b * TDEC + tt;
            if (tv != 0) { g_nll[idx] = m + logf(s) - sl[tv]; g_msk[idx] = 1.f; }
            else         { g_nll[idx] = 0.f;                  g_msk[idx] = 0.f; }
        }
    }
}

// ---------------- the single persistent kernel ------------------------------
__global__ void __launch_bounds__(256, 1) persist_kernel(
    const float* __restrict__ C,       const int* __restrict__ C_pad,
    const int* __restrict__ E,         const float* __restrict__ E_emb,
    const float* __restrict__ enc_Wih, const float* __restrict__ enc_Whh,
    const float* __restrict__ enc_bih, const float* __restrict__ enc_bhh,
    const float* __restrict__ dec_Wih, const float* __restrict__ dec_Whh,
    const float* __restrict__ dec_bih, const float* __restrict__ dec_bhh,
    const float* __restrict__ att_W,   const float* __restrict__ out_W,
    const float* __restrict__ out_b,   const float* __restrict__ voc_W,
    const float* __restrict__ voc_b,   float* __restrict__ out)
{
    extern __shared__ __align__(16) float4 dsm[];
    float4* Wp  = dsm;
    float4* Ab  = dsm + 9216;
    float*  scr = (float*)(dsm + 10240);

    int bid = blockIdx.x, tid = threadIdx.x;
    int lane = tid & 31, w = tid >> 5;
    int mh = bid & 1, nb = bid >> 1;

    // ---- init state ----
    for (int i = bid * 256 + tid; i < BHS; i += NBLK * 256) { g_h[0][i] = 0.f; g_c[i] = 0.f; }
    float* vpf = (float*)g_vp;
    for (int i = bid * 256 + tid; i < 4 * BHS; i += NBLK * 256) vpf[i] = 0.f;
    gsync();

    // ---- encoder ----
    pack_W(Wp, nb, 80, Vz, enc_Wih, Vz, enc_Whh, Hz);
    __syncthreads();
    float biasE[2][4];
    load_bias(biasE, enc_bih, enc_bhh, nb);
    for (int t = 0; t < LCz; t++) {
        const float* hin = g_h[t & 1];
        float* hout = g_h[1 - (t & 1)];
        gates_step<false>(Wp, Ab, C, t, hin, hout, mh, nb, biasE);
        gsync();
    }

    // ---- decoder ----
    pack_W(Wp, nb, 144, Vz + Hz, dec_Wih, Vz + Hz, dec_Whh, Hz);
    __syncthreads();
    float biasD[2][4];
    load_bias(biasD, dec_bih, dec_bhh, nb);

    int ks = bid & 3, kr = bid >> 2;
    int km0 = (kr & 3) * 32, kn0 = (kr >> 2) * 64;
    for (int t = 0; t < TDEC; t++) {
        const float* hin = g_h[t & 1];
        float* hout = g_h[1 - (t & 1)];

        // P1: gates (tf32 mma) + cell
        gates_step<true>(Wp, Ab, E_emb, t, hin, hout, mh, nb, biasD);
        gsync();

        // P2: q partials (K-split x4)
        {
            float acc[2][4] = {};
            seg_accum(hout + km0 * Hz + ks * 128, Hz,
                      att_W + (size_t)kn0 * Hz + ks * 128, Hz, 128, acc, scr);
            plain_epi(acc, g_qp[ks], km0, kn0, nullptr);
        }
        gsync();

        // P3: attention for batch=bid + logits/CE of step t-1
        attn_block(bid, C_pad, scr);
        if (t > 0) logits_ce(bid, t - 1, E, voc_W, voc_b, scr);
        gsync();

        // P4: out-proj partials (K-split x4); bias folded into split 0
        {
            const float* Asrc = (ks < 2) ? hout : g_attn;
            int koff = (ks & 1) * 256;
            float acc[2][4] = {};
            seg_accum(Asrc + km0 * Hz + koff, Hz,
                      out_W + (size_t)kn0 * (2 * Hz) + ks * 256, 2 * Hz, 256, acc, scr);
            plain_epi(acc, g_vp[ks], km0, kn0, (ks == 0) ? out_b : nullptr);
        }
        gsync();
    }

    // ---- last step's logits/CE ----
    logits_ce(bid, TDEC - 1, E, voc_W, voc_b, scr);
    gsync();

    // ---- deterministic reduction ----
    {
        float s = 0.f, c = 0.f;
        for (int i = tid; i < TDEC; i += 256) {
            s += g_nll[bid * TDEC + i];
            c += g_msk[bid * TDEC + i];
        }
        #pragma unroll
        for (int o = 16; o > 0; o >>= 1) {
            s += __shfl_xor_sync(0xffffffffu, s, o);
            c += __shfl_xor_sync(0xffffffffu, c, o);
        }
        __syncthreads();
        if (lane == 0) { scr[w] = s; scr[8 + w] = c; }
        __syncthreads();
        if (tid == 0) {
            float ts = 0.f, tc = 0.f;
            for (int i = 0; i < 8; i++) { ts += scr[i]; tc += scr[8 + i]; }
            g_ps[bid] = ts; g_pc[bid] = tc;
        }
    }
    gsync();
    if (bid == 0 && tid == 0) {
        float ts = 0.f, tc = 0.f;
        for (int i = 0; i < NBLK; i++) { ts += g_ps[i]; tc += g_pc[i]; }
        out[0] = ts / fmaxf(tc, 1.f);
    }
}

// ---------------- host entry (single launch => 1-node graph) ----------------
extern "C" void kernel_launch(void* const* d_in, const int* in_sizes, int n_in,
                              void* d_out, int out_size)
{
    cudaFuncSetAttribute((const void*)persist_kernel,
                         cudaFuncAttributeMaxDynamicSharedMemorySize, SMEM_BYTES);
    persist_kernel<<<NBLK, 256, SMEM_BYTES>>>(
        (const float*)d_in[0],  (const int*)d_in[1],
        (const int*)d_in[2],    (const float*)d_in[3],
        (const float*)d_in[4],  (const float*)d_in[5],
        (const float*)d_in[6],  (const float*)d_in[7],
        (const float*)d_in[8],  (const float*)d_in[9],
        (const float*)d_in[10], (const float*)d_in[11],
        (const float*)d_in[12], (const float*)d_in[13],
        (const float*)d_in[14], (const float*)d_in[15],
        (const float*)d_in[16], (float*)d_out);
}